// round 1
// baseline (speedup 1.0000x reference)
#include <cuda_runtime.h>

// Problem constants (fixed by setup_inputs)
#define BB 4
#define NN 3000
#define MM 3000
#define TILE 128
#define HALF_OUT (BB * NN * 2)   // 24000
#define TOT_OUT  (2 * HALF_OUT)  // 48000

// Scratch accumulators: [0 .. HALF_OUT)   = S0[b][n][c] (sum over m of sin/cos)
//                       [HALF_OUT .. )    = S1[b][m][c] (sum over n of sin/cos)
__device__ float g_acc[TOT_OUT];

__device__ __forceinline__ float fsqrt_ap(float x) {
    float r; asm("sqrt.approx.f32 %0, %1;" : "=f"(r) : "f"(x)); return r;
}
__device__ __forceinline__ float fsin_ap(float x) {
    float r; asm("sin.approx.f32 %0, %1;" : "=f"(r) : "f"(x)); return r;
}
__device__ __forceinline__ float fcos_ap(float x) {
    float r; asm("cos.approx.f32 %0, %1;" : "=f"(r) : "f"(x)); return r;
}

__global__ void zero_kernel() {
    int i = blockIdx.x * blockDim.x + threadIdx.x;
    if (i < TOT_OUT) g_acc[i] = 0.0f;
}

__global__ __launch_bounds__(256, 2) void pair_kernel(
    const float* __restrict__ p0, const float* __restrict__ p1)
{
    const int b  = blockIdx.z;
    const int n0 = blockIdx.y * TILE;
    const int m0 = blockIdx.x * TILE;

    __shared__ float2 sA[TILE];
    __shared__ float2 sB[TILE];
    __shared__ float2 red[TILE][17];   // padded: float-offset = 34*r + 2*k + comp (bank-clean)

    const int tid = threadIdx.x;
    const int tx = tid & 15;
    const int ty = tid >> 4;

    // Cooperative tile load: threads 0..127 load A rows, 128..255 load B cols.
    if (tid < TILE) {
        int n = n0 + tid;
        sA[tid] = (n < NN) ? reinterpret_cast<const float2*>(p0)[b * NN + n]
                           : make_float2(0.0f, 0.0f);
    } else {
        int m = m0 + (tid - TILE);
        sB[tid - TILE] = (m < MM) ? reinterpret_cast<const float2*>(p1)[b * MM + m]
                                  : make_float2(0.0f, 0.0f);
    }
    __syncthreads();

    float ax[8], ay[8], bx[8], by[8];
    float rS[8], rC[8], cS[8], cC[8];
#pragma unroll
    for (int i = 0; i < 8; i++) {
        float2 v = sA[ty + 16 * i];
        ax[i] = v.x; ay[i] = v.y;
        rS[i] = 0.0f; rC[i] = 0.0f;
    }
#pragma unroll
    for (int j = 0; j < 8; j++) {
        float2 v = sB[tx + 16 * j];
        bx[j] = v.x; by[j] = v.y;
        cS[j] = 0.0f; cC[j] = 0.0f;
    }

    const bool full = (n0 + TILE <= NN) && (m0 + TILE <= MM);
    if (full) {
#pragma unroll
        for (int i = 0; i < 8; i++) {
#pragma unroll
            for (int j = 0; j < 8; j++) {
                float xy = fmaf(ay[i], by[j], ax[i] * bx[j]);
                float t  = fmaxf(fmaf(-2.0f, xy, 2.0f), 0.0f);
                float d  = fsqrt_ap(t);
                float s  = fsin_ap(d);
                float c  = fcos_ap(d);
                rS[i] += s; rC[i] += c;
                cS[j] += s; cC[j] += c;
            }
        }
    } else {
        float mi[8], mj[8];
#pragma unroll
        for (int i = 0; i < 8; i++) mi[i] = (n0 + ty + 16 * i < NN) ? 1.0f : 0.0f;
#pragma unroll
        for (int j = 0; j < 8; j++) mj[j] = (m0 + tx + 16 * j < MM) ? 1.0f : 0.0f;
#pragma unroll
        for (int i = 0; i < 8; i++) {
#pragma unroll
            for (int j = 0; j < 8; j++) {
                float xy = fmaf(ay[i], by[j], ax[i] * bx[j]);
                float t  = fmaxf(fmaf(-2.0f, xy, 2.0f), 0.0f);
                float d  = fsqrt_ap(t);
                float s  = fsin_ap(d);
                float c  = fcos_ap(d);
                float m  = mi[i] * mj[j];
                rS[i] = fmaf(m, s, rS[i]); rC[i] = fmaf(m, c, rC[i]);
                cS[j] = fmaf(m, s, cS[j]); cC[j] = fmaf(m, c, cC[j]);
            }
        }
    }

    // --- Stage A: row sums (reduce across tx) ---
#pragma unroll
    for (int i = 0; i < 8; i++)
        red[ty + 16 * i][tx] = make_float2(rS[i], rC[i]);
    __syncthreads();
    {
        int row  = tid >> 1;
        int comp = tid & 1;
        float sum = 0.0f;
#pragma unroll
        for (int k = 0; k < 16; k++)
            sum += reinterpret_cast<const float*>(&red[row][k])[comp];
        int n = n0 + row;
        if (n < NN) atomicAdd(&g_acc[(b * NN + n) * 2 + comp], sum);
    }
    __syncthreads();

    // --- Stage B: col sums (reduce across ty) ---
#pragma unroll
    for (int j = 0; j < 8; j++)
        red[tx + 16 * j][ty] = make_float2(cS[j], cC[j]);
    __syncthreads();
    {
        int col  = tid >> 1;
        int comp = tid & 1;
        float sum = 0.0f;
#pragma unroll
        for (int k = 0; k < 16; k++)
            sum += reinterpret_cast<const float*>(&red[col][k])[comp];
        int m = m0 + col;
        if (m < MM) atomicAdd(&g_acc[HALF_OUT + (b * MM + m) * 2 + comp], sum);
    }
}

__global__ void finalize_kernel(const float* __restrict__ p0,
                                const float* __restrict__ p1,
                                float* __restrict__ out)
{
    int i = blockIdx.x * blockDim.x + threadIdx.x;
    if (i < HALF_OUT) {
        out[i] = p0[i] * g_acc[i];
    } else if (i < TOT_OUT) {
        out[i] = p1[i - HALF_OUT] * g_acc[i];
    }
}

extern "C" void kernel_launch(void* const* d_in, const int* in_sizes, int n_in,
                              void* d_out, int out_size)
{
    const float* p0 = (const float*)d_in[0];
    const float* p1 = (const float*)d_in[1];
    float* out = (float*)d_out;

    zero_kernel<<<(TOT_OUT + 255) / 256, 256>>>();

    dim3 grid((MM + TILE - 1) / TILE, (NN + TILE - 1) / TILE, BB);
    pair_kernel<<<grid, 256>>>(p0, p1);

    finalize_kernel<<<(TOT_OUT + 255) / 256, 256>>>(p0, p1, out);
}

// round 2
// speedup vs baseline: 1.0009x; 1.0009x over previous
#include <cuda_runtime.h>

// Problem constants (fixed by setup_inputs)
#define BB 4
#define NN 3000
#define MM 3000
#define TILE 128
#define HALF_OUT (BB * NN * 2)   // 24000
#define TOT_OUT  (2 * HALF_OUT)  // 48000

// Scratch accumulators: [0 .. HALF_OUT)   = S0[b][n][c] (sum over m of sin/cos)
//                       [HALF_OUT .. )    = S1[b][m][c] (sum over n of sin/cos)
__device__ float g_acc[TOT_OUT];

__device__ __forceinline__ float fsqrt_ap(float x) {
    float r; asm("sqrt.approx.f32 %0, %1;" : "=f"(r) : "f"(x)); return r;
}
__device__ __forceinline__ float fsin_ap(float x) {
    float r; asm("sin.approx.f32 %0, %1;" : "=f"(r) : "f"(x)); return r;
}
__device__ __forceinline__ float fcos_ap(float x) {
    float r; asm("cos.approx.f32 %0, %1;" : "=f"(r) : "f"(x)); return r;
}

__global__ void zero_kernel() {
    int i = blockIdx.x * blockDim.x + threadIdx.x;
    if (i < TOT_OUT) g_acc[i] = 0.0f;
}

__global__ __launch_bounds__(256, 2) void pair_kernel(
    const float* __restrict__ p0, const float* __restrict__ p1)
{
    const int b  = blockIdx.z;
    const int n0 = blockIdx.y * TILE;
    const int m0 = blockIdx.x * TILE;

    __shared__ float2 sA[TILE];
    __shared__ float2 sB[TILE];
    __shared__ float2 red[TILE][17];   // padded: float-offset = 34*r + 2*k + comp (bank-clean)

    const int tid = threadIdx.x;
    const int tx = tid & 15;
    const int ty = tid >> 4;

    // Cooperative tile load: threads 0..127 load A rows, 128..255 load B cols.
    if (tid < TILE) {
        int n = n0 + tid;
        sA[tid] = (n < NN) ? reinterpret_cast<const float2*>(p0)[b * NN + n]
                           : make_float2(0.0f, 0.0f);
    } else {
        int m = m0 + (tid - TILE);
        sB[tid - TILE] = (m < MM) ? reinterpret_cast<const float2*>(p1)[b * MM + m]
                                  : make_float2(0.0f, 0.0f);
    }
    __syncthreads();

    float ax[8], ay[8], bx[8], by[8];
    float rS[8], rC[8], cS[8], cC[8];
#pragma unroll
    for (int i = 0; i < 8; i++) {
        float2 v = sA[ty + 16 * i];
        ax[i] = v.x; ay[i] = v.y;
        rS[i] = 0.0f; rC[i] = 0.0f;
    }
#pragma unroll
    for (int j = 0; j < 8; j++) {
        float2 v = sB[tx + 16 * j];
        bx[j] = v.x; by[j] = v.y;
        cS[j] = 0.0f; cC[j] = 0.0f;
    }

    const bool full = (n0 + TILE <= NN) && (m0 + TILE <= MM);
    if (full) {
#pragma unroll
        for (int i = 0; i < 8; i++) {
#pragma unroll
            for (int j = 0; j < 8; j++) {
                float xy = fmaf(ay[i], by[j], ax[i] * bx[j]);
                float t  = fmaxf(fmaf(-2.0f, xy, 2.0f), 0.0f);
                float d  = fsqrt_ap(t);
                float s  = fsin_ap(d);
                float c  = fcos_ap(d);
                rS[i] += s; rC[i] += c;
                cS[j] += s; cC[j] += c;
            }
        }
    } else {
        float mi[8], mj[8];
#pragma unroll
        for (int i = 0; i < 8; i++) mi[i] = (n0 + ty + 16 * i < NN) ? 1.0f : 0.0f;
#pragma unroll
        for (int j = 0; j < 8; j++) mj[j] = (m0 + tx + 16 * j < MM) ? 1.0f : 0.0f;
#pragma unroll
        for (int i = 0; i < 8; i++) {
#pragma unroll
            for (int j = 0; j < 8; j++) {
                float xy = fmaf(ay[i], by[j], ax[i] * bx[j]);
                float t  = fmaxf(fmaf(-2.0f, xy, 2.0f), 0.0f);
                float d  = fsqrt_ap(t);
                float s  = fsin_ap(d);
                float c  = fcos_ap(d);
                float m  = mi[i] * mj[j];
                rS[i] = fmaf(m, s, rS[i]); rC[i] = fmaf(m, c, rC[i]);
                cS[j] = fmaf(m, s, cS[j]); cC[j] = fmaf(m, c, cC[j]);
            }
        }
    }

    // --- Stage A: row sums (reduce across tx) ---
#pragma unroll
    for (int i = 0; i < 8; i++)
        red[ty + 16 * i][tx] = make_float2(rS[i], rC[i]);
    __syncthreads();
    {
        int row  = tid >> 1;
        int comp = tid & 1;
        float sum = 0.0f;
#pragma unroll
        for (int k = 0; k < 16; k++)
            sum += reinterpret_cast<const float*>(&red[row][k])[comp];
        int n = n0 + row;
        if (n < NN) atomicAdd(&g_acc[(b * NN + n) * 2 + comp], sum);
    }
    __syncthreads();

    // --- Stage B: col sums (reduce across ty) ---
#pragma unroll
    for (int j = 0; j < 8; j++)
        red[tx + 16 * j][ty] = make_float2(cS[j], cC[j]);
    __syncthreads();
    {
        int col  = tid >> 1;
        int comp = tid & 1;
        float sum = 0.0f;
#pragma unroll
        for (int k = 0; k < 16; k++)
            sum += reinterpret_cast<const float*>(&red[col][k])[comp];
        int m = m0 + col;
        if (m < MM) atomicAdd(&g_acc[HALF_OUT + (b * MM + m) * 2 + comp], sum);
    }
}

__global__ void finalize_kernel(const float* __restrict__ p0,
                                const float* __restrict__ p1,
                                float* __restrict__ out)
{
    int i = blockIdx.x * blockDim.x + threadIdx.x;
    if (i < HALF_OUT) {
        out[i] = p0[i] * g_acc[i];
    } else if (i < TOT_OUT) {
        out[i] = p1[i - HALF_OUT] * g_acc[i];
    }
}

extern "C" void kernel_launch(void* const* d_in, const int* in_sizes, int n_in,
                              void* d_out, int out_size)
{
    const float* p0 = (const float*)d_in[0];
    const float* p1 = (const float*)d_in[1];
    float* out = (float*)d_out;

    zero_kernel<<<(TOT_OUT + 255) / 256, 256>>>();

    dim3 grid((MM + TILE - 1) / TILE, (NN + TILE - 1) / TILE, BB);
    pair_kernel<<<grid, 256>>>(p0, p1);

    finalize_kernel<<<(TOT_OUT + 255) / 256, 256>>>(p0, p1, out);
}

// round 3
// speedup vs baseline: 1.0626x; 1.0616x over previous
#include <cuda_runtime.h>

// Problem constants (fixed by setup_inputs)
#define BB 4
#define NN 3000
#define MM 3000
#define TILE 128
#define HALF_OUT (BB * NN * 2)   // 24000
#define TOT_OUT  (2 * HALF_OUT)  // 48000

__device__ __forceinline__ float fsqrt_ap(float x) {
    float r; asm("sqrt.approx.f32 %0, %1;" : "=f"(r) : "f"(x)); return r;
}
__device__ __forceinline__ float fsin_ap(float x) {
    float r; asm("sin.approx.f32 %0, %1;" : "=f"(r) : "f"(x)); return r;
}
__device__ __forceinline__ float fcos_ap(float x) {
    float r; asm("cos.approx.f32 %0, %1;" : "=f"(r) : "f"(x)); return r;
}

// Zero the (poisoned) output buffer: 48000 floats = 12000 float4.
__global__ void zero_out_kernel(float4* __restrict__ out4) {
    int i = blockIdx.x * blockDim.x + threadIdx.x;
    if (i < TOT_OUT / 4) out4[i] = make_float4(0.f, 0.f, 0.f, 0.f);
}

// One 128x128 tile of the (B,N,M) pair grid per block. Each block:
//  - computes sin/cos of pair distances,
//  - reduces row partials (over m) and col partials (over n),
//  - pre-multiplies by p0[n] / p1[m] and atomicAdds straight into out.
__global__ __launch_bounds__(256, 2) void pair_kernel(
    const float* __restrict__ p0, const float* __restrict__ p1,
    float* __restrict__ out)
{
    const int b  = blockIdx.z;
    const int n0 = blockIdx.y * TILE;
    const int m0 = blockIdx.x * TILE;

    __shared__ float2 sA[TILE];
    __shared__ float2 sB[TILE];
    __shared__ float2 red[TILE][17];   // padded: float-offset = 34*r + 2*k + comp (bank-clean)

    const int tid = threadIdx.x;
    const int tx = tid & 15;
    const int ty = tid >> 4;

    // Cooperative tile load: threads 0..127 load A rows, 128..255 load B cols.
    if (tid < TILE) {
        int n = n0 + tid;
        sA[tid] = (n < NN) ? reinterpret_cast<const float2*>(p0)[b * NN + n]
                           : make_float2(0.0f, 0.0f);
    } else {
        int m = m0 + (tid - TILE);
        sB[tid - TILE] = (m < MM) ? reinterpret_cast<const float2*>(p1)[b * MM + m]
                                  : make_float2(0.0f, 0.0f);
    }
    __syncthreads();

    float axn[8], ayn[8], bx[8], by[8];
    float rS[8], rC[8], cS[8], cC[8];
#pragma unroll
    for (int i = 0; i < 8; i++) {
        float2 v = sA[ty + 16 * i];
        axn[i] = -2.0f * v.x; ayn[i] = -2.0f * v.y;   // fold the 2-2xy scaling
        rS[i] = 0.0f; rC[i] = 0.0f;
    }
#pragma unroll
    for (int j = 0; j < 8; j++) {
        float2 v = sB[tx + 16 * j];
        bx[j] = v.x; by[j] = v.y;
        cS[j] = 0.0f; cC[j] = 0.0f;
    }

    const bool full = (n0 + TILE <= NN) && (m0 + TILE <= MM);
    if (full) {
#pragma unroll
        for (int i = 0; i < 8; i++) {
#pragma unroll
            for (int j = 0; j < 8; j++) {
                float t = fmaf(axn[i], bx[j], fmaf(ayn[i], by[j], 2.0f));
                t = fmaxf(t, 0.0f);
                float d = fsqrt_ap(t);
                float s = fsin_ap(d);
                float c = fcos_ap(d);
                rS[i] += s; rC[i] += c;
                cS[j] += s; cC[j] += c;
            }
        }
    } else {
        float mi[8], mj[8];
#pragma unroll
        for (int i = 0; i < 8; i++) mi[i] = (n0 + ty + 16 * i < NN) ? 1.0f : 0.0f;
#pragma unroll
        for (int j = 0; j < 8; j++) mj[j] = (m0 + tx + 16 * j < MM) ? 1.0f : 0.0f;
#pragma unroll
        for (int i = 0; i < 8; i++) {
#pragma unroll
            for (int j = 0; j < 8; j++) {
                float t = fmaf(axn[i], bx[j], fmaf(ayn[i], by[j], 2.0f));
                t = fmaxf(t, 0.0f);
                float d = fsqrt_ap(t);
                float s = fsin_ap(d);
                float c = fcos_ap(d);
                float m = mi[i] * mj[j];
                rS[i] = fmaf(m, s, rS[i]); rC[i] = fmaf(m, c, rC[i]);
                cS[j] = fmaf(m, s, cS[j]); cC[j] = fmaf(m, c, cC[j]);
            }
        }
    }

    // --- Stage A: row sums (reduce across tx), premultiply by p0, add to out ---
#pragma unroll
    for (int i = 0; i < 8; i++)
        red[ty + 16 * i][tx] = make_float2(rS[i], rC[i]);
    __syncthreads();
    {
        int row  = tid >> 1;
        int comp = tid & 1;
        float sum = 0.0f;
#pragma unroll
        for (int k = 0; k < 16; k++)
            sum += reinterpret_cast<const float*>(&red[row][k])[comp];
        int n = n0 + row;
        if (n < NN) {
            float pv = reinterpret_cast<const float*>(&sA[row])[comp];
            atomicAdd(&out[(b * NN + n) * 2 + comp], pv * sum);
        }
    }
    __syncthreads();

    // --- Stage B: col sums (reduce across ty), premultiply by p1, add to out ---
#pragma unroll
    for (int j = 0; j < 8; j++)
        red[tx + 16 * j][ty] = make_float2(cS[j], cC[j]);
    __syncthreads();
    {
        int col  = tid >> 1;
        int comp = tid & 1;
        float sum = 0.0f;
#pragma unroll
        for (int k = 0; k < 16; k++)
            sum += reinterpret_cast<const float*>(&red[col][k])[comp];
        int m = m0 + col;
        if (m < MM) {
            float pv = reinterpret_cast<const float*>(&sB[col])[comp];
            atomicAdd(&out[HALF_OUT + (b * MM + m) * 2 + comp], pv * sum);
        }
    }
}

extern "C" void kernel_launch(void* const* d_in, const int* in_sizes, int n_in,
                              void* d_out, int out_size)
{
    const float* p0 = (const float*)d_in[0];
    const float* p1 = (const float*)d_in[1];
    float* out = (float*)d_out;

    zero_out_kernel<<<(TOT_OUT / 4 + 255) / 256, 256>>>((float4*)out);

    dim3 grid((MM + TILE - 1) / TILE, (NN + TILE - 1) / TILE, BB);
    pair_kernel<<<grid, 256>>>(p0, p1, out);
}